// round 2
// baseline (speedup 1.0000x reference)
#include <cuda_runtime.h>
#include <math.h>

#define Sdim 1024
#define Bdim 8
#define Edim 512
#define Hdim 8
#define Ddim 64
#define Ndim 64   // B*H

// ---------------- scratch (static device allocations are allowed) ----------------
__device__ float g_q[(size_t)Ndim*Sdim*Ddim];        // [n][s][d] 16MB
__device__ float g_k[(size_t)Ndim*Sdim*Ddim];
__device__ float g_v[(size_t)Ndim*Sdim*Ddim];
__device__ float g_bias[(size_t)Sdim*Sdim*Ndim];     // [j][i][n] 256MB
__device__ float g_attn[(size_t)Ndim*Sdim*Sdim];     // [n][i][j] 256MB
__device__ float g_ctx[(size_t)Sdim*Bdim*Edim];      // [s][b][e] == [m][e], m=s*B+b
__device__ float g_x[(size_t)Sdim*Bdim*Edim];

// =======================================================================
// K1: QKV projection.  C[m,o] = sum_e X[m,e]*W[o,e] + bias[o]
// stored as q[n=(b*H+h)][s][d] with m=(s,b), o=(h,d)
// =======================================================================
__global__ void __launch_bounds__(256) proj_kernel(const float* __restrict__ X,
    const float* __restrict__ W, const float* __restrict__ bias, int sel)
{
    __shared__ float Xs[16][132];
    __shared__ float Ws[16][68];
    int tid = threadIdx.x;
    int m0 = blockIdx.x * 128;
    int o0 = blockIdx.y * 64;
    int ty = tid >> 4, tx = tid & 15;
    float acc[8][4];
    #pragma unroll
    for (int i=0;i<8;i++)
        #pragma unroll
        for (int j=0;j<4;j++) acc[i][j]=0.f;

    for (int k0 = 0; k0 < Edim; k0 += 16) {
        #pragma unroll
        for (int r = 0; r < 2; r++) {
            int row = (tid >> 2) + r*64;
            int col = (tid & 3) * 4;
            float4 v = *(const float4*)&X[(size_t)(m0+row)*Edim + k0 + col];
            Xs[col][row]=v.x; Xs[col+1][row]=v.y; Xs[col+2][row]=v.z; Xs[col+3][row]=v.w;
        }
        {
            int row = tid >> 2;
            int col = (tid & 3) * 4;
            float4 v = *(const float4*)&W[(size_t)(o0+row)*Edim + k0 + col];
            Ws[col][row]=v.x; Ws[col+1][row]=v.y; Ws[col+2][row]=v.z; Ws[col+3][row]=v.w;
        }
        __syncthreads();
        #pragma unroll
        for (int k=0;k<16;k++){
            float a[8], b[4];
            #pragma unroll
            for(int i=0;i<8;i++) a[i]=Xs[k][ty*8+i];
            #pragma unroll
            for(int j=0;j<4;j++) b[j]=Ws[k][tx*4+j];
            #pragma unroll
            for(int i=0;i<8;i++)
                #pragma unroll
                for(int j=0;j<4;j++) acc[i][j] = fmaf(a[i], b[j], acc[i][j]);
        }
        __syncthreads();
    }
    float* out = (sel==0) ? g_q : ((sel==1) ? g_k : g_v);
    #pragma unroll
    for (int i=0;i<8;i++){
        int m = m0 + ty*8 + i;
        int s = m >> 3, b = m & 7;
        #pragma unroll
        for (int j=0;j<4;j++){
            int o = o0 + tx*4 + j;
            int h = o >> 6, d = o & 63;
            out[(size_t)((b*Hdim+h)*Sdim + s)*Ddim + d] = acc[i][j] + bias[o];
        }
    }
}

// =======================================================================
// K2: edge-key bias.  bias[n,i,j] = sum_d edge_key[j,i,d] * q[n,j,d]
// per fixed j: [64i x 64d] @ [64d x 64n] GEMM -> g_bias[j][i][n]
// =======================================================================
__global__ void __launch_bounds__(256) biasgemm_kernel(const float* __restrict__ ek)
{
    __shared__ float EKs[64][65];   // [d][i]
    __shared__ float QJs[64][65];   // [d][n]
    int tid = threadIdx.x;
    int i0 = blockIdx.x * 64;
    int j  = blockIdx.y;
    const float* EK = ek + (size_t)j*Sdim*Ddim + (size_t)i0*Ddim;  // [64][64] contiguous
    #pragma unroll
    for (int r=0;r<16;r++){
        int idx = tid + r*256;
        int row = idx >> 6, d = idx & 63;
        EKs[d][row] = EK[idx];
        QJs[d][row] = g_q[(size_t)row*Sdim*Ddim + (size_t)j*Ddim + d]; // row is n
    }
    __syncthreads();
    int ty = tid>>4, tx = tid&15;
    float acc[4][4] = {};
    #pragma unroll
    for (int d=0; d<64; d++){
        float a[4], b[4];
        #pragma unroll
        for (int i=0;i<4;i++) a[i]=EKs[d][ty*4+i];
        #pragma unroll
        for (int jn=0;jn<4;jn++) b[jn]=QJs[d][tx*4+jn];
        #pragma unroll
        for (int i=0;i<4;i++)
            #pragma unroll
            for (int jn=0;jn<4;jn++) acc[i][jn] = fmaf(a[i], b[jn], acc[i][jn]);
    }
    #pragma unroll
    for (int i=0;i<4;i++){
        int gi = i0 + ty*4 + i;
        float4 v = make_float4(acc[i][0],acc[i][1],acc[i][2],acc[i][3]);
        *(float4*)&g_bias[(size_t)j*Sdim*Ndim + (size_t)gi*Ndim + tx*4] = v;
    }
}

// =======================================================================
// K3: scores.  logit[n,i,j] = (q[n,i,:].k[n,j,:] + bias[n,i,j]) * scale, masked
// =======================================================================
__global__ void __launch_bounds__(256) score_kernel(const int* __restrict__ mask)
{
    __shared__ float Qs[64][65];  // [d][i]
    __shared__ float Ks[64][65];  // [d][j]
    int tid = threadIdx.x;
    int n  = blockIdx.x;
    int i0 = blockIdx.y*64, j0 = blockIdx.z*64;
    #pragma unroll
    for (int r=0;r<16;r++){
        int idx = tid + r*256;
        int row = idx>>6, d = idx&63;
        Qs[d][row] = g_q[(size_t)n*Sdim*Ddim + (size_t)(i0+row)*Ddim + d];
        Ks[d][row] = g_k[(size_t)n*Sdim*Ddim + (size_t)(j0+row)*Ddim + d];
    }
    __syncthreads();
    int ty=tid>>4, tx=tid&15;
    float acc[4][4] = {};
    #pragma unroll
    for (int d=0; d<64; d++){
        float a[4], b[4];
        #pragma unroll
        for (int i=0;i<4;i++) a[i]=Qs[d][ty*4+i];
        #pragma unroll
        for (int j=0;j<4;j++) b[j]=Ks[d][tx*4+j];
        #pragma unroll
        for (int i=0;i<4;i++)
            #pragma unroll
            for (int j=0;j<4;j++) acc[i][j] = fmaf(a[i], b[j], acc[i][j]);
    }
    #pragma unroll
    for (int i=0;i<4;i++){
        int gi = i0+ty*4+i;
        int gj0 = j0+tx*4;
        int4 mv = *(const int4*)&mask[(size_t)n*Sdim*Sdim + (size_t)gi*Sdim + gj0];
        float4 o;
        o.x = mv.x ? -1e30f : (acc[i][0] + g_bias[(size_t)(gj0+0)*Sdim*Ndim + (size_t)gi*Ndim + n])*0.125f;
        o.y = mv.y ? -1e30f : (acc[i][1] + g_bias[(size_t)(gj0+1)*Sdim*Ndim + (size_t)gi*Ndim + n])*0.125f;
        o.z = mv.z ? -1e30f : (acc[i][2] + g_bias[(size_t)(gj0+2)*Sdim*Ndim + (size_t)gi*Ndim + n])*0.125f;
        o.w = mv.w ? -1e30f : (acc[i][3] + g_bias[(size_t)(gj0+3)*Sdim*Ndim + (size_t)gi*Ndim + n])*0.125f;
        *(float4*)&g_attn[(size_t)n*Sdim*Sdim + (size_t)gi*Sdim + gj0] = o;
    }
}

// =======================================================================
// K4: softmax over j (row length 1024)
// =======================================================================
__global__ void __launch_bounds__(256) softmax_kernel()
{
    int i = blockIdx.x, n = blockIdx.y;
    float* row = g_attn + (size_t)n*Sdim*Sdim + (size_t)i*Sdim;
    int tid = threadIdx.x;
    float4 v = *(float4*)&row[tid*4];
    float mx = fmaxf(fmaxf(v.x,v.y),fmaxf(v.z,v.w));
    __shared__ float red[256];
    red[tid]=mx; __syncthreads();
    for (int s2=128;s2>0;s2>>=1){ if(tid<s2) red[tid]=fmaxf(red[tid],red[tid+s2]); __syncthreads(); }
    mx = red[0]; __syncthreads();
    v.x=expf(v.x-mx); v.y=expf(v.y-mx); v.z=expf(v.z-mx); v.w=expf(v.w-mx);
    red[tid]=v.x+v.y+v.z+v.w; __syncthreads();
    for (int s2=128;s2>0;s2>>=1){ if(tid<s2) red[tid]+=red[tid+s2]; __syncthreads(); }
    float inv = 1.0f/red[0];
    v.x*=inv; v.y*=inv; v.z*=inv; v.w*=inv;
    *(float4*)&row[tid*4] = v;
}

// =======================================================================
// K5a: PV.  ctx[s=i][n*64+d] = sum_j attn[n,i,j]*v[n,j,d]
// =======================================================================
__global__ void __launch_bounds__(256) pv_kernel()
{
    __shared__ float As[32][65];  // [jj][i]
    __shared__ float Vs[32][65];  // [jj][d]
    int tid=threadIdx.x;
    int i0 = blockIdx.x*64;
    int n  = blockIdx.y;
    int ty=tid>>4, tx=tid&15;
    float acc[4][4]={};
    for (int j0=0;j0<Sdim;j0+=32){
        #pragma unroll
        for (int r=0;r<8;r++){
            int idx = tid + r*256;
            int ii = idx>>5, jj = idx&31;
            As[jj][ii] = g_attn[(size_t)n*Sdim*Sdim + (size_t)(i0+ii)*Sdim + j0+jj];
        }
        #pragma unroll
        for (int r=0;r<8;r++){
            int idx = tid + r*256;
            int jj = idx>>6, d = idx&63;
            Vs[jj][d] = g_v[(size_t)n*Sdim*Ddim + (size_t)(j0+jj)*Ddim + d];
        }
        __syncthreads();
        #pragma unroll
        for (int jj=0;jj<32;jj++){
            float a[4],b[4];
            #pragma unroll
            for (int i=0;i<4;i++) a[i]=As[jj][ty*4+i];
            #pragma unroll
            for (int j=0;j<4;j++) b[j]=Vs[jj][tx*4+j];
            #pragma unroll
            for (int i=0;i<4;i++)
                #pragma unroll
                for (int j=0;j<4;j++) acc[i][j] = fmaf(a[i], b[j], acc[i][j]);
        }
        __syncthreads();
    }
    #pragma unroll
    for (int i=0;i<4;i++){
        int s = i0+ty*4+i;
        *(float4*)&g_ctx[(size_t)s*(Bdim*Edim) + n*64 + tx*4]
            = make_float4(acc[i][0],acc[i][1],acc[i][2],acc[i][3]);
    }
}

// =======================================================================
// K5b: edge-value.  ctx[i][n*64+d] += sum_j attn[n,i,j]*edge_value[i,j,d]
// per fixed i: [64n x 1024j] @ [1024j x 64d]
// =======================================================================
__global__ void __launch_bounds__(256) ev_kernel(const float* __restrict__ ev)
{
    __shared__ float As[32][65];  // [jj][n]
    __shared__ float Es[32][65];  // [jj][d]
    int tid=threadIdx.x;
    int i = blockIdx.x;
    int ty=tid>>4, tx=tid&15;
    float acc[4][4]={};
    for (int j0=0;j0<Sdim;j0+=32){
        #pragma unroll
        for (int r=0;r<8;r++){
            int idx=tid+r*256;
            int nn=idx>>5, jj=idx&31;
            As[jj][nn] = g_attn[(size_t)nn*Sdim*Sdim + (size_t)i*Sdim + j0+jj];
        }
        #pragma unroll
        for (int r=0;r<8;r++){
            int idx=tid+r*256;
            int jj=idx>>6, d=idx&63;
            Es[jj][d] = ev[(size_t)i*Sdim*Ddim + (size_t)(j0+jj)*Ddim + d];
        }
        __syncthreads();
        #pragma unroll
        for (int jj=0;jj<32;jj++){
            float a[4],b[4];
            #pragma unroll
            for (int in=0;in<4;in++) a[in]=As[jj][ty*4+in];
            #pragma unroll
            for (int j=0;j<4;j++) b[j]=Es[jj][tx*4+j];
            #pragma unroll
            for (int in=0;in<4;in++)
                #pragma unroll
                for (int j=0;j<4;j++) acc[in][j] = fmaf(a[in], b[j], acc[in][j]);
        }
        __syncthreads();
    }
    #pragma unroll
    for (int in=0;in<4;in++){
        int nn = ty*4+in;
        float4* p = (float4*)&g_ctx[(size_t)i*(Bdim*Edim) + nn*64 + tx*4];
        float4 old = *p;
        *p = make_float4(old.x+acc[in][0], old.y+acc[in][1], old.z+acc[in][2], old.w+acc[in][3]);
    }
}

// =======================================================================
// K6: output projection + residual.  g_x[m,o] = ctx[m,:].Wo[o,:] + bo[o] + query[m,o]
// =======================================================================
__global__ void __launch_bounds__(256) outproj_kernel(const float* __restrict__ W,
    const float* __restrict__ bias, const float* __restrict__ resid)
{
    __shared__ float Xs[16][132];
    __shared__ float Ws[16][68];
    int tid = threadIdx.x;
    int m0 = blockIdx.x * 128;
    int o0 = blockIdx.y * 64;
    int ty = tid >> 4, tx = tid & 15;
    float acc[8][4];
    #pragma unroll
    for (int i=0;i<8;i++)
        #pragma unroll
        for (int j=0;j<4;j++) acc[i][j]=0.f;

    for (int k0 = 0; k0 < Edim; k0 += 16) {
        #pragma unroll
        for (int r = 0; r < 2; r++) {
            int row = (tid >> 2) + r*64;
            int col = (tid & 3) * 4;
            float4 v = *(const float4*)&g_ctx[(size_t)(m0+row)*Edim + k0 + col];
            Xs[col][row]=v.x; Xs[col+1][row]=v.y; Xs[col+2][row]=v.z; Xs[col+3][row]=v.w;
        }
        {
            int row = tid >> 2;
            int col = (tid & 3) * 4;
            float4 v = *(const float4*)&W[(size_t)(o0+row)*Edim + k0 + col];
            Ws[col][row]=v.x; Ws[col+1][row]=v.y; Ws[col+2][row]=v.z; Ws[col+3][row]=v.w;
        }
        __syncthreads();
        #pragma unroll
        for (int k=0;k<16;k++){
            float a[8], b[4];
            #pragma unroll
            for(int i=0;i<8;i++) a[i]=Xs[k][ty*8+i];
            #pragma unroll
            for(int j=0;j<4;j++) b[j]=Ws[k][tx*4+j];
            #pragma unroll
            for(int i=0;i<8;i++)
                #pragma unroll
                for(int j=0;j<4;j++) acc[i][j] = fmaf(a[i], b[j], acc[i][j]);
        }
        __syncthreads();
    }
    #pragma unroll
    for (int i=0;i<8;i++){
        int m = m0 + ty*8 + i;
        #pragma unroll
        for (int j=0;j<4;j++){
            int o = o0 + tx*4 + j;
            g_x[(size_t)m*Edim + o] = acc[i][j] + bias[o] + resid[(size_t)m*Edim + o];
        }
    }
}

// =======================================================================
// K7: LayerNorm over last dim (512)
// =======================================================================
__global__ void __launch_bounds__(256) ln_kernel(const float* __restrict__ gamma,
     const float* __restrict__ beta, float* __restrict__ out)
{
    int m = blockIdx.x, tid = threadIdx.x;
    float a = g_x[(size_t)m*Edim + tid];
    float b = g_x[(size_t)m*Edim + 256 + tid];
    __shared__ float s1[256], s2[256];
    s1[tid] = a+b; s2[tid] = a*a + b*b;
    __syncthreads();
    for (int s=128;s>0;s>>=1){
        if(tid<s){ s1[tid]+=s1[tid+s]; s2[tid]+=s2[tid+s]; }
        __syncthreads();
    }
    float mean = s1[0] * (1.0f/512.0f);
    float var  = s2[0] * (1.0f/512.0f) - mean*mean;
    float rstd = rsqrtf(var + 1e-5f);
    out[(size_t)m*Edim + tid]       = gamma[tid]*(a-mean)*rstd + beta[tid];
    out[(size_t)m*Edim + 256 + tid] = gamma[256+tid]*(b-mean)*rstd + beta[256+tid];
}

// =======================================================================
extern "C" void kernel_launch(void* const* d_in, const int* in_sizes, int n_in,
                              void* d_out, int out_size)
{
    const float* query      = (const float*)d_in[0];
    const float* key        = (const float*)d_in[1];
    const float* value      = (const float*)d_in[2];
    const float* edge_key   = (const float*)d_in[3];
    const float* edge_value = (const float*)d_in[4];
    const int*   mask       = (const int*)  d_in[5];
    // num_heads scalar may or may not be materialized as an input
    int base = (n_in == 17) ? 7 : 6;
    const float* Wq = (const float*)d_in[base+0];
    const float* bq = (const float*)d_in[base+1];
    const float* Wk = (const float*)d_in[base+2];
    const float* bk = (const float*)d_in[base+3];
    const float* Wv = (const float*)d_in[base+4];
    const float* bv = (const float*)d_in[base+5];
    const float* Wo = (const float*)d_in[base+6];
    const float* bo = (const float*)d_in[base+7];
    const float* gamma = (const float*)d_in[base+8];
    const float* beta  = (const float*)d_in[base+9];

    dim3 gp(64, 8);
    proj_kernel<<<gp,256>>>(query, Wq, bq, 0);
    proj_kernel<<<gp,256>>>(key,   Wk, bk, 1);
    proj_kernel<<<gp,256>>>(value, Wv, bv, 2);
    biasgemm_kernel<<<dim3(16,1024),256>>>(edge_key);
    score_kernel<<<dim3(64,16,16),256>>>(mask);
    softmax_kernel<<<dim3(1024,64),256>>>();
    pv_kernel<<<dim3(16,64),256>>>();
    ev_kernel<<<dim3(1024),256>>>(edge_value);
    outproj_kernel<<<gp,256>>>(Wo, bo, query);
    ln_kernel<<<dim3(8192),256>>>(gamma, beta, (float*)d_out);
}